// round 1
// baseline (speedup 1.0000x reference)
#include <cuda_runtime.h>
#include <math_constants.h>

#define D   256
#define K   1024
#define TM  64          // rows per block
#define TNT 256         // codes per tile
#define NTILES (K/TNT)  // 4
#define KC  32          // d-chunk

#define ZT_STRIDE 68    // padded stride for zt[d][row]  (bank-conflict avoidance, 16B-aligned rows)
#define CT_STRIDE 260   // padded stride for ct[d][code]

__device__ float  g_cnorm[K];
__device__ int    g_idx[65536];
__device__ double g_loss_sum;

// ---- packed f32x2 helpers (FFMA2 only reachable via PTX) ----
__device__ __forceinline__ unsigned long long pack2(float x, float y){
    unsigned long long r;
    asm("mov.b64 %0, {%1, %2};" : "=l"(r) : "f"(x), "f"(y));
    return r;
}
__device__ __forceinline__ void unpack2(unsigned long long v, float& x, float& y){
    asm("mov.b64 {%0, %1}, %2;" : "=f"(x), "=f"(y) : "l"(v));
}
__device__ __forceinline__ unsigned long long ffma2(unsigned long long a,
                                                    unsigned long long b,
                                                    unsigned long long c){
    unsigned long long d_;
    asm("fma.rn.f32x2 %0, %1, %2, %3;" : "=l"(d_) : "l"(a), "l"(b), "l"(c));
    return d_;
}

// ---------------------------------------------------------------------------
// Kernel 1: codebook squared norms + zero the loss accumulator
// grid = K/8 blocks of 256 (8 warps, one code per warp)
// ---------------------------------------------------------------------------
__global__ void k_setup(const float* __restrict__ cb){
    if (blockIdx.x == 0 && threadIdx.x == 0) g_loss_sum = 0.0;
    int w    = threadIdx.x >> 5;
    int lane = threadIdx.x & 31;
    int code = blockIdx.x * 8 + w;
    const float* c = cb + (size_t)code * D;
    float s = 0.f;
    #pragma unroll
    for (int j = 0; j < 8; j++){
        float v = c[lane + 32 * j];
        s = __fmaf_rn(v, v, s);
    }
    #pragma unroll
    for (int off = 16; off; off >>= 1)
        s += __shfl_xor_sync(0xffffffffu, s, off);
    if (lane == 0) g_cnorm[code] = s;
}

// ---------------------------------------------------------------------------
// Kernel 2: fused distance + argmin.
// Block: 256 threads (tx = tid&31 over codes, ty = tid>>5 over rows).
// Each block owns TM=64 rows, iterates all K codes in NTILES tiles of 256.
// Per-thread register tile: 8 rows x 8 codes, codes packed as f32x2 pairs.
// Score is computed EXACTLY as the reference:  fl( fl(znorm+cnorm) - 2*dot ).
// Tie-break: first (lowest) code index, matching jnp.argmin.
// ---------------------------------------------------------------------------
__global__ __launch_bounds__(256, 2) void k_argmin(
    const float* __restrict__ Z, const float* __restrict__ CB,
    float* __restrict__ out_idx)
{
    extern __shared__ float sm[];
    float* zt = sm;                         // [D][ZT_STRIDE] transposed z tile
    float* ct = zt + D * ZT_STRIDE;         // [KC][CT_STRIDE] transposed code chunk
    float* cn = ct + KC * CT_STRIDE;        // [TNT] cnorm tile
    float* zn = cn + TNT;                   // [TM] z norms
    float* rs = ct;                         // alias (final reduce scores) [TM][32]
    int*   ri = (int*)(ct + TM * 32);       // alias (final reduce indices)

    const int tid  = threadIdx.x;
    const int tx   = tid & 31;
    const int ty   = tid >> 5;
    const int row0 = blockIdx.x * TM;

    // --- load full z tile (64 rows x 256) transposed into smem ---
    {
        const float4* Z4 = (const float4*)(Z + (size_t)row0 * D);
        #pragma unroll
        for (int k = 0; k < 16; k++){
            int idx = tid + k * 256;
            int r   = idx >> 6;       // row 0..63
            int g   = idx & 63;       // float4 within row
            float4 v = Z4[r * 64 + g];
            int d0 = g * 4;
            zt[(d0 + 0) * ZT_STRIDE + r] = v.x;
            zt[(d0 + 1) * ZT_STRIDE + r] = v.y;
            zt[(d0 + 2) * ZT_STRIDE + r] = v.z;
            zt[(d0 + 3) * ZT_STRIDE + r] = v.w;
        }
    }
    __syncthreads();

    // --- znorm per row: LLVM-style 8 strided accumulators + pairwise-halving tree,
    //     no FMA contraction (mimic jnp.sum(z**2) on CPU) ---
    if (tid < TM){
        const float* zr = Z + (size_t)(row0 + tid) * D;
        float a0=0.f,a1=0.f,a2=0.f,a3=0.f,a4=0.f,a5=0.f,a6=0.f,a7=0.f;
        for (int i = 0; i < D; i += 8){
            a0 = __fadd_rn(a0, __fmul_rn(zr[i+0], zr[i+0]));
            a1 = __fadd_rn(a1, __fmul_rn(zr[i+1], zr[i+1]));
            a2 = __fadd_rn(a2, __fmul_rn(zr[i+2], zr[i+2]));
            a3 = __fadd_rn(a3, __fmul_rn(zr[i+3], zr[i+3]));
            a4 = __fadd_rn(a4, __fmul_rn(zr[i+4], zr[i+4]));
            a5 = __fadd_rn(a5, __fmul_rn(zr[i+5], zr[i+5]));
            a6 = __fadd_rn(a6, __fmul_rn(zr[i+6], zr[i+6]));
            a7 = __fadd_rn(a7, __fmul_rn(zr[i+7], zr[i+7]));
        }
        float b0 = __fadd_rn(a0, a4), b1 = __fadd_rn(a1, a5);
        float b2 = __fadd_rn(a2, a6), b3 = __fadd_rn(a3, a7);
        zn[tid] = __fadd_rn(__fadd_rn(b0, b2), __fadd_rn(b1, b3));
    }

    float best_s[8];
    int   best_i[8];
    #pragma unroll
    for (int r = 0; r < 8; r++){ best_s[r] = CUDART_INF_F; best_i[r] = 0; }

    const float4* CB4 = (const float4*)CB;

    for (int t = 0; t < NTILES; t++){
        const int c0 = t * TNT;
        __syncthreads();                      // cn of previous tile fully consumed
        cn[tid] = g_cnorm[c0 + tid];          // 256 threads load 256 norms

        unsigned long long acc[8][4];
        #pragma unroll
        for (int r = 0; r < 8; r++)
            #pragma unroll
            for (int p = 0; p < 4; p++) acc[r][p] = 0ull;

        for (int d0 = 0; d0 < D; d0 += KC){
            __syncthreads();
            // load code chunk (256 codes x 32 d) transposed
            #pragma unroll
            for (int k = 0; k < 8; k++){
                int idx  = tid + k * 256;
                int code = idx >> 3;         // 0..255
                int g    = idx & 7;          // float4 within chunk
                float4 v = CB4[(size_t)(c0 + code) * 64 + (d0 >> 2) + g];
                int dd = g * 4;
                ct[(dd + 0) * CT_STRIDE + code] = v.x;
                ct[(dd + 1) * CT_STRIDE + code] = v.y;
                ct[(dd + 2) * CT_STRIDE + code] = v.z;
                ct[(dd + 3) * CT_STRIDE + code] = v.w;
            }
            __syncthreads();

            #pragma unroll 8
            for (int kk = 0; kk < KC; kk++){
                const float* ztrow = zt + (d0 + kk) * ZT_STRIDE + ty * 8;
                float4 za = *(const float4*)(ztrow);
                float4 zb = *(const float4*)(ztrow + 4);
                ulonglong2 cA = *(const ulonglong2*)(ct + kk * CT_STRIDE + tx * 4);
                ulonglong2 cB = *(const ulonglong2*)(ct + kk * CT_STRIDE + 128 + tx * 4);
                unsigned long long zp[8];
                zp[0] = pack2(za.x, za.x); zp[1] = pack2(za.y, za.y);
                zp[2] = pack2(za.z, za.z); zp[3] = pack2(za.w, za.w);
                zp[4] = pack2(zb.x, zb.x); zp[5] = pack2(zb.y, zb.y);
                zp[6] = pack2(zb.z, zb.z); zp[7] = pack2(zb.w, zb.w);
                #pragma unroll
                for (int r = 0; r < 8; r++){
                    acc[r][0] = ffma2(zp[r], cA.x, acc[r][0]);
                    acc[r][1] = ffma2(zp[r], cA.y, acc[r][1]);
                    acc[r][2] = ffma2(zp[r], cB.x, acc[r][2]);
                    acc[r][3] = ffma2(zp[r], cB.y, acc[r][3]);
                }
            }
        }

        // epilogue: score = fl( fl(zn + cn) - 2*dot ); 2*dot is exact so fmaf(-2,dot,t)
        // is the same single-rounded value the reference produces.
        #pragma unroll
        for (int r = 0; r < 8; r++){
            float zn_r = zn[ty * 8 + r];
            #pragma unroll
            for (int p = 0; p < 4; p++){
                float dlo, dhi;
                unpack2(acc[r][p], dlo, dhi);
                int clocal = (p < 2) ? (tx * 4 + p * 2) : (128 + tx * 4 + (p - 2) * 2);
                float t1 = __fadd_rn(zn_r, cn[clocal]);
                float s1 = __fmaf_rn(-2.0f, dlo, t1);
                if (s1 < best_s[r]) { best_s[r] = s1; best_i[r] = c0 + clocal; }
                float t2 = __fadd_rn(zn_r, cn[clocal + 1]);
                float s2 = __fmaf_rn(-2.0f, dhi, t2);
                if (s2 < best_s[r]) { best_s[r] = s2; best_i[r] = c0 + clocal + 1; }
            }
        }
    }

    // --- cross-thread (tx) reduce per row with lexicographic (score, index) min ---
    __syncthreads();
    #pragma unroll
    for (int r = 0; r < 8; r++){
        rs[(ty * 8 + r) * 32 + tx] = best_s[r];
        ri[(ty * 8 + r) * 32 + tx] = best_i[r];
    }
    __syncthreads();
    if (tid < TM){
        float bs = CUDART_INF_F;
        int   bi = K;
        #pragma unroll
        for (int x = 0; x < 32; x++){
            float s = rs[tid * 32 + x];
            int   i = ri[tid * 32 + x];
            if (s < bs || (s == bs && i < bi)){ bs = s; bi = i; }
        }
        g_idx[row0 + tid]  = bi;
        out_idx[row0 + tid] = (float)bi;
    }
}

// ---------------------------------------------------------------------------
// Kernel 3: gather z_q, write straight-through output exactly as the reference
// (z_e + fl(z_q - z_e)), and accumulate sum of squared diffs for the loss.
// ---------------------------------------------------------------------------
__global__ void k_gather(const float4* __restrict__ Z4,
                         const float4* __restrict__ CB4,
                         float4* __restrict__ O4)
{
    __shared__ float wsum[8];
    int e   = blockIdx.x * blockDim.x + threadIdx.x;  // float4 index
    int row = e >> 6;                                  // 64 float4 per row
    int c   = e & 63;
    int idx = g_idx[row];
    float4 z = Z4[e];
    float4 q = CB4[(size_t)idx * 64 + c];

    float d0 = __fsub_rn(q.x, z.x);
    float d1 = __fsub_rn(q.y, z.y);
    float d2 = __fsub_rn(q.z, z.z);
    float d3 = __fsub_rn(q.w, z.w);

    float4 o;
    o.x = __fadd_rn(z.x, d0);
    o.y = __fadd_rn(z.y, d1);
    o.z = __fadd_rn(z.z, d2);
    o.w = __fadd_rn(z.w, d3);
    O4[e] = o;

    float s = d0 * d0 + d1 * d1 + d2 * d2 + d3 * d3;
    #pragma unroll
    for (int off = 16; off; off >>= 1)
        s += __shfl_xor_sync(0xffffffffu, s, off);
    int lane = threadIdx.x & 31, w = threadIdx.x >> 5;
    if (lane == 0) wsum[w] = s;
    __syncthreads();
    if (threadIdx.x == 0){
        float bsum = 0.f;
        #pragma unroll
        for (int i = 0; i < 8; i++) bsum += wsum[i];
        atomicAdd(&g_loss_sum, (double)bsum);
    }
}

// ---------------------------------------------------------------------------
// Kernel 4: finalize loss:  vq = mean + 0.25*mean
// ---------------------------------------------------------------------------
__global__ void k_loss(float* __restrict__ out_loss, int n_total){
    double m  = g_loss_sum / (double)n_total;
    float  cb = (float)m;
    out_loss[0] = __fadd_rn(cb, __fmul_rn(0.25f, cb));
}

// ---------------------------------------------------------------------------
extern "C" void kernel_launch(void* const* d_in, const int* in_sizes, int n_in,
                              void* d_out, int out_size)
{
    const float* Z  = (const float*)d_in[0];
    const float* CB = (const float*)d_in[1];
    float* out = (float*)d_out;
    const int n_z = in_sizes[0];      // 16777216
    const int N   = n_z >> 8;         // 65536 rows

    k_setup<<<K / 8, 256>>>(CB);

    const int smem = (D * ZT_STRIDE + KC * CT_STRIDE + TNT + TM) * (int)sizeof(float);
    cudaFuncSetAttribute(k_argmin, cudaFuncAttributeMaxDynamicSharedMemorySize, smem);
    // out layout: [ z_q_st (n_z) | vq_loss (1) | indices (N) ]
    k_argmin<<<N / TM, 256, smem>>>(Z, CB, out + n_z + 1);

    k_gather<<<(n_z / 4) / 256, 256>>>((const float4*)Z, (const float4*)CB, (float4*)out);

    k_loss<<<1, 1>>>(out + n_z, n_z);
}